// round 12
// baseline (speedup 1.0000x reference)
#include <cuda_runtime.h>
#include <math.h>

#define N_NODESC 20000
#define N_EDGESC 640000
#define FEATC    128
#define N_RBFC   20
#define CUTOFFC  5.0f
#define PIF      3.14159265358979323846f

typedef unsigned long long u64;

// ---------------- f32x2 packed helpers ----------------
__device__ __forceinline__ u64 pack2(float lo, float hi) {
    u64 r; asm("mov.b64 %0, {%1,%2};" : "=l"(r) : "f"(lo), "f"(hi)); return r;
}
__device__ __forceinline__ void unpack2(u64 p, float& lo, float& hi) {
    asm("mov.b64 {%0,%1}, %2;" : "=f"(lo), "=f"(hi) : "l"(p));
}
__device__ __forceinline__ u64 fma2(u64 a, u64 b, u64 c) {
    u64 d; asm("fma.rn.f32x2 %0, %1, %2, %3;" : "=l"(d) : "l"(a), "l"(b), "l"(c)); return d;
}
__device__ __forceinline__ u64 add2(u64 a, u64 b) {
    u64 d; asm("add.rn.f32x2 %0, %1, %2;" : "=l"(d) : "l"(a), "l"(b)); return d;
}

// ---------------- scratch (__device__ globals; no allocation) ----------------
__device__ __align__(16) float g_phi[N_NODESC * 3 * FEATC];   // phi_node, [N,384]
__device__ __align__(16) float g_v0[N_NODESC * FEATC];        // v_j SoA planes
__device__ __align__(16) float g_v1[N_NODESC * FEATC];
__device__ __align__(16) float g_v2[N_NODESC * FEATC];
__device__ __align__(16) int   g_count[N_NODESC];
__device__ __align__(16) int   g_cursor[N_NODESC];
__device__ __align__(16) int   g_rowptr[N_NODESC + 1];
__device__ __align__(16) int   g_eid[N_EDGESC];
__device__ __align__(16) int   g_src[N_EDGESC];
__device__ __align__(16) int   g_dst[N_EDGESC];
__device__ int g_flag;   // 0 -> nbrs is int64, nonzero -> int32

// ---------------- zero counters ----------------
__global__ void zero_kernel() {
    int i = blockIdx.x * blockDim.x + threadIdx.x;
    if (i < N_NODESC) { g_count[i] = 0; g_cursor[i] = 0; }
    if (i == 0) g_flag = 0;
}

// ---------------- dtype probe ----------------
__global__ void detect_kernel(const int* __restrict__ nbrs32) {
    int t = threadIdx.x;
    int v = nbrs32[2 * t + 1];
    __shared__ int red[1024];
    red[t] = v;
    __syncthreads();
    for (int off = 512; off > 0; off >>= 1) {
        if (t < off) red[t] |= red[t + off];
        __syncthreads();
    }
    if (t == 0) g_flag = red[0];
}

// ---------------- normalize indices to int32 SoA + degree count ----------------
__global__ void extract_kernel(const void* __restrict__ nbrs) {
    int e = blockIdx.x * blockDim.x + threadIdx.x;
    if (e >= N_EDGESC) return;
    int si, di;
    if (g_flag != 0) {
        const int* p = (const int*)nbrs;
        si = p[2 * e]; di = p[2 * e + 1];
    } else {
        const long long* p = (const long long*)nbrs;
        si = (int)p[2 * (long long)e]; di = (int)p[2 * (long long)e + 1];
    }
    g_src[e] = si;
    g_dst[e] = di;
    atomicAdd(&g_count[si], 1);
}

// ---------------- v_j [N,128,3] -> SoA planes [N,128] ----------------
// smem-staged: coalesced float4 row read, conflict-free stride-3 LDS (3 coprime 32).
__global__ __launch_bounds__(128) void vtrans_kernel(const float* __restrict__ v_j) {
    __shared__ __align__(16) float row[384];
    int j = blockIdx.x;
    const float4* src = (const float4*)(v_j + (size_t)j * 384);
    float4* dst = (float4*)row;
    for (int i = threadIdx.x; i < 96; i += 128) dst[i] = src[i];
    __syncthreads();
    int f = threadIdx.x;
    g_v0[(size_t)j * FEATC + f] = row[3 * f];
    g_v1[(size_t)j * FEATC + f] = row[3 * f + 1];
    g_v2[(size_t)j * FEATC + f] = row[3 * f + 2];
}

// ---------------- fused node MLP: phi = silu(s@W1+b1)@W2 + b2 ----------------
// 128 threads, 32 nodes/block. Thread tile: 4 nodes x 8 cols, f32x2 packed FMA.
#define SPAD 132
__global__ __launch_bounds__(128) void phi_kernel(
    const float* __restrict__ s,
    const float* __restrict__ W1, const float* __restrict__ b1,
    const float* __restrict__ W2, const float* __restrict__ b2)
{
    __shared__ __align__(16) float s_sm[32][SPAD];
    __shared__ __align__(16) float h_sm[32][SPAD];
    int tid = threadIdx.x;
    int node0 = blockIdx.x * 32;

    {
        const float4* s4 = (const float4*)(s + (size_t)node0 * FEATC);
        for (int idx = tid; idx < 32 * 32; idx += 128) {
            int row = idx >> 5, c = idx & 31;
            *(float4*)&s_sm[row][c * 4] = s4[row * 32 + c];
        }
    }
    __syncthreads();

    int cx = tid & 15;    // col octet: cols 8cx..8cx+7
    int ny = tid >> 4;    // node quad: rows 4ny..4ny+3

    // ---- stage 1: h = silu(s@W1 + b1) ----
    {
        u64 acc[4][4];
        #pragma unroll
        for (int i = 0; i < 4; i++)
            #pragma unroll
            for (int p = 0; p < 4; p++) acc[i][p] = 0ull;
        const ulonglong2* W1q = (const ulonglong2*)W1;  // 32 u2 per row
        #pragma unroll 4
        for (int k = 0; k < FEATC; k += 2) {
            ulonglong2 wA0 = W1q[(size_t)k * 32 + 2 * cx];
            ulonglong2 wA1 = W1q[(size_t)k * 32 + 2 * cx + 1];
            ulonglong2 wB0 = W1q[(size_t)(k + 1) * 32 + 2 * cx];
            ulonglong2 wB1 = W1q[(size_t)(k + 1) * 32 + 2 * cx + 1];
            #pragma unroll
            for (int i = 0; i < 4; i++) {
                float2 a2 = *(const float2*)&s_sm[ny * 4 + i][k];
                u64 aA = pack2(a2.x, a2.x);
                u64 aB = pack2(a2.y, a2.y);
                acc[i][0] = fma2(aA, wA0.x, acc[i][0]);
                acc[i][1] = fma2(aA, wA0.y, acc[i][1]);
                acc[i][2] = fma2(aA, wA1.x, acc[i][2]);
                acc[i][3] = fma2(aA, wA1.y, acc[i][3]);
                acc[i][0] = fma2(aB, wB0.x, acc[i][0]);
                acc[i][1] = fma2(aB, wB0.y, acc[i][1]);
                acc[i][2] = fma2(aB, wB1.x, acc[i][2]);
                acc[i][3] = fma2(aB, wB1.y, acc[i][3]);
            }
        }
        float2 bv[4];
        #pragma unroll
        for (int p = 0; p < 4; p++) bv[p] = *(const float2*)&b1[cx * 8 + p * 2];
        #pragma unroll
        for (int i = 0; i < 4; i++) {
            float h[8];
            #pragma unroll
            for (int p = 0; p < 4; p++) {
                float lo, hi; unpack2(acc[i][p], lo, hi);
                float x0 = lo + bv[p].x, x1 = hi + bv[p].y;
                h[2 * p]     = x0 / (1.0f + expf(-x0));
                h[2 * p + 1] = x1 / (1.0f + expf(-x1));
            }
            *(float4*)&h_sm[ny * 4 + i][cx * 8]     = make_float4(h[0], h[1], h[2], h[3]);
            *(float4*)&h_sm[ny * 4 + i][cx * 8 + 4] = make_float4(h[4], h[5], h[6], h[7]);
        }
    }
    __syncthreads();

    // ---- stage 2: phi = h@W2 + b2 (3 col-groups of 128) ----
    const ulonglong2* W2q = (const ulonglong2*)W2;  // 96 u2 per row
    for (int g = 0; g < 3; g++) {
        u64 acc[4][4];
        #pragma unroll
        for (int i = 0; i < 4; i++)
            #pragma unroll
            for (int p = 0; p < 4; p++) acc[i][p] = 0ull;
        #pragma unroll 4
        for (int k = 0; k < FEATC; k += 2) {
            ulonglong2 wA0 = W2q[(size_t)k * 96 + g * 32 + 2 * cx];
            ulonglong2 wA1 = W2q[(size_t)k * 96 + g * 32 + 2 * cx + 1];
            ulonglong2 wB0 = W2q[(size_t)(k + 1) * 96 + g * 32 + 2 * cx];
            ulonglong2 wB1 = W2q[(size_t)(k + 1) * 96 + g * 32 + 2 * cx + 1];
            #pragma unroll
            for (int i = 0; i < 4; i++) {
                float2 a2 = *(const float2*)&h_sm[ny * 4 + i][k];
                u64 aA = pack2(a2.x, a2.x);
                u64 aB = pack2(a2.y, a2.y);
                acc[i][0] = fma2(aA, wA0.x, acc[i][0]);
                acc[i][1] = fma2(aA, wA0.y, acc[i][1]);
                acc[i][2] = fma2(aA, wA1.x, acc[i][2]);
                acc[i][3] = fma2(aA, wA1.y, acc[i][3]);
                acc[i][0] = fma2(aB, wB0.x, acc[i][0]);
                acc[i][1] = fma2(aB, wB0.y, acc[i][1]);
                acc[i][2] = fma2(aB, wB1.x, acc[i][2]);
                acc[i][3] = fma2(aB, wB1.y, acc[i][3]);
            }
        }
        float2 bv[4];
        #pragma unroll
        for (int p = 0; p < 4; p++) bv[p] = *(const float2*)&b2[g * 128 + cx * 8 + p * 2];
        #pragma unroll
        for (int i = 0; i < 4; i++) {
            float o[8];
            #pragma unroll
            for (int p = 0; p < 4; p++) {
                float lo, hi; unpack2(acc[i][p], lo, hi);
                o[2 * p]     = lo + bv[p].x;
                o[2 * p + 1] = hi + bv[p].y;
            }
            float* dst = &g_phi[(size_t)(node0 + ny * 4 + i) * 384 + g * 128 + cx * 8];
            *(float4*)dst       = make_float4(o[0], o[1], o[2], o[3]);
            *(float4*)(dst + 4) = make_float4(o[4], o[5], o[6], o[7]);
        }
    }
}

// ---------------- CSR scan (2-level shfl scan, 20 items/thread) ----------------
__global__ void scan_kernel() {
    const int PER = 20;
    int t = threadIdx.x;
    int lane = t & 31, wid = t >> 5;
    int base = t * PER;
    int pre[PER];
    int s = 0;
    #pragma unroll
    for (int i = 0; i < PER; i++) {
        int idx = base + i;
        int v = (idx < N_NODESC) ? g_count[idx] : 0;
        pre[i] = s;
        s += v;
    }
    int x = s;
    #pragma unroll
    for (int off = 1; off < 32; off <<= 1) {
        int y = __shfl_up_sync(0xffffffffu, x, off);
        if (lane >= off) x += y;
    }
    __shared__ int wsum[32];
    if (lane == 31) wsum[wid] = x;
    __syncthreads();
    if (wid == 0) {
        int w = wsum[lane];
        #pragma unroll
        for (int off = 1; off < 32; off <<= 1) {
            int y = __shfl_up_sync(0xffffffffu, w, off);
            if (lane >= off) w += y;
        }
        wsum[lane] = w;
    }
    __syncthreads();
    int thread_pref = (x - s) + (wid > 0 ? wsum[wid - 1] : 0);
    #pragma unroll
    for (int i = 0; i < PER; i++) {
        int idx = base + i;
        if (idx < N_NODESC) g_rowptr[idx] = thread_pref + pre[i];
    }
    if (t == 1023) g_rowptr[N_NODESC] = wsum[31];
}

__global__ void scatter_kernel() {
    int e = blockIdx.x * blockDim.x + threadIdx.x;
    if (e < N_EDGESC) {
        int i = g_src[e];
        int pos = g_rowptr[i] + atomicAdd(&g_cursor[i], 1);
        g_eid[pos] = e;
    }
}

// ---------------- node-parallel accumulate ----------------
// 128 threads, 1 feature/thread. FFMA2 dot, depth-2 prefetch.
// All six gather loads are now single-line coalesced (phi rows + v SoA planes).
#define STAGE 64
#define GPAD  24
__global__ __launch_bounds__(128, 4) void accum_kernel(
    const float* __restrict__ r_ij,
    const float* __restrict__ Wd, const float* __restrict__ bd,
    float* __restrict__ out_s, float* __restrict__ out_v)
{
    __shared__ __align__(16) float sm_g[STAGE][GPAD];   // rbf_k = sin(kx)/d
    __shared__ __align__(16) float4 sm_geo[STAGE];      // u0,u1,u2,env
    __shared__ int sm_j[STAGE];

    int f = threadIdx.x;

    u64 wdA[10], wdB[10], wdC[10];
    #pragma unroll
    for (int i = 0; i < 10; i++) {
        wdA[i] = pack2(Wd[(2 * i) * 384 + f],       Wd[(2 * i + 1) * 384 + f]);
        wdB[i] = pack2(Wd[(2 * i) * 384 + 128 + f], Wd[(2 * i + 1) * 384 + 128 + f]);
        wdC[i] = pack2(Wd[(2 * i) * 384 + 256 + f], Wd[(2 * i + 1) * 384 + 256 + f]);
    }
    float bd0 = bd[f], bd1 = bd[128 + f], bd2 = bd[256 + f];

    for (int node = blockIdx.x; node < N_NODESC; node += gridDim.x) {
        int start = g_rowptr[node];
        int end   = g_rowptr[node + 1];
        float accs = 0.0f, av0 = 0.0f, av1 = 0.0f, av2 = 0.0f;

        for (int base = start; base < end; base += STAGE) {
            int n = end - base; if (n > STAGE) n = STAGE;
            __syncthreads();
            // phase A: stage per-edge geometry + raw rbf (one thread per edge)
            if (f < n) {
                int eid = g_eid[base + f];
                float r0 = r_ij[3 * (size_t)eid + 0];
                float r1 = r_ij[3 * (size_t)eid + 1];
                float r2 = r_ij[3 * (size_t)eid + 2];
                float d2 = r0 * r0 + r1 * r1 + r2 * r2 + 3e-15f;
                float d  = sqrtf(d2);
                float rinv = 1.0f / d;
                float x = (PIF / CUTOFFC) * d;
                float sx, cxx;
                sincosf(x, &sx, &cxx);
                float env = (d < CUTOFFC) ? 0.5f * (cxx + 1.0f) : 0.0f;
                sm_geo[f] = make_float4(r0 * rinv, r1 * rinv, r2 * rinv, env);
                float twoc = 2.0f * cxx;
                float sp = 0.0f, sc = sx;
                #pragma unroll
                for (int k = 0; k < N_RBFC; k++) {
                    sm_g[f][k] = sc * rinv;  // env applied at consume time
                    float sn = twoc * sc - sp;
                    sp = sc; sc = sn;
                }
                sm_j[f] = g_dst[eid];
            }
            __syncthreads();

            // phase B: depth-2 prefetched accumulate, all loads coalesced
            float p0[2], p1[2], p2[2], vx[2], vy[2], vz[2];
            {
                int j0 = sm_j[0];
                const float* ph = g_phi + (size_t)j0 * 384 + f;
                p0[0] = ph[0]; p1[0] = ph[128]; p2[0] = ph[256];
                size_t vo = (size_t)j0 * FEATC + f;
                vx[0] = g_v0[vo]; vy[0] = g_v1[vo]; vz[0] = g_v2[vo];
            }
            if (n > 1) {
                int j1 = sm_j[1];
                const float* ph = g_phi + (size_t)j1 * 384 + f;
                p0[1] = ph[0]; p1[1] = ph[128]; p2[1] = ph[256];
                size_t vo = (size_t)j1 * FEATC + f;
                vx[1] = g_v0[vo]; vy[1] = g_v1[vo]; vz[1] = g_v2[vo];
            }
            #pragma unroll 2
            for (int e = 0; e < n; e++) {
                int slot = e & 1;
                float cp0 = p0[slot], cp1 = p1[slot], cp2 = p2[slot];
                float cvx = vx[slot], cvy = vy[slot], cvz = vz[slot];
                if (e + 2 < n) {
                    int jn = sm_j[e + 2];
                    const float* ph = g_phi + (size_t)jn * 384 + f;
                    p0[slot] = ph[0]; p1[slot] = ph[128]; p2[slot] = ph[256];
                    size_t vo = (size_t)jn * FEATC + f;
                    vx[slot] = g_v0[vo]; vy[slot] = g_v1[vo]; vz[slot] = g_v2[vo];
                }
                const ulonglong2* gq = (const ulonglong2*)&sm_g[e][0];
                ulonglong2 qa = gq[0], qb = gq[1], qc = gq[2], qd = gq[3], qe = gq[4];
                u64 a0, a1, b0, b1, c0, c1;
                a0 = fma2(qa.x, wdA[0], 0ull); a1 = fma2(qa.y, wdA[1], 0ull);
                b0 = fma2(qa.x, wdB[0], 0ull); b1 = fma2(qa.y, wdB[1], 0ull);
                c0 = fma2(qa.x, wdC[0], 0ull); c1 = fma2(qa.y, wdC[1], 0ull);
                a0 = fma2(qb.x, wdA[2], a0);   a1 = fma2(qb.y, wdA[3], a1);
                b0 = fma2(qb.x, wdB[2], b0);   b1 = fma2(qb.y, wdB[3], b1);
                c0 = fma2(qb.x, wdC[2], c0);   c1 = fma2(qb.y, wdC[3], c1);
                a0 = fma2(qc.x, wdA[4], a0);   a1 = fma2(qc.y, wdA[5], a1);
                b0 = fma2(qc.x, wdB[4], b0);   b1 = fma2(qc.y, wdB[5], b1);
                c0 = fma2(qc.x, wdC[4], c0);   c1 = fma2(qc.y, wdC[5], c1);
                a0 = fma2(qd.x, wdA[6], a0);   a1 = fma2(qd.y, wdA[7], a1);
                b0 = fma2(qd.x, wdB[6], b0);   b1 = fma2(qd.y, wdB[7], b1);
                c0 = fma2(qd.x, wdC[6], c0);   c1 = fma2(qd.y, wdC[7], c1);
                a0 = fma2(qe.x, wdA[8], a0);   a1 = fma2(qe.y, wdA[9], a1);
                b0 = fma2(qe.x, wdB[8], b0);   b1 = fma2(qe.y, wdB[9], b1);
                c0 = fma2(qe.x, wdC[8], c0);   c1 = fma2(qe.y, wdC[9], c1);

                float4 geo = sm_geo[e];
                float lo, hi;
                unpack2(add2(a0, a1), lo, hi); float ws0 = (lo + hi + bd0) * geo.w;
                unpack2(add2(b0, b1), lo, hi); float ws1 = (lo + hi + bd1) * geo.w;
                unpack2(add2(c0, c1), lo, hi); float ws2 = (lo + hi + bd2) * geo.w;

                float i0 = cp0 * ws0;
                float i2 = cp2 * ws2;
                accs += cp1 * ws1;
                av0 += i2 * geo.x; av0 += i0 * cvx;
                av1 += i2 * geo.y; av1 += i0 * cvy;
                av2 += i2 * geo.z; av2 += i0 * cvz;
            }
        }
        out_s[(size_t)node * FEATC + f] = accs;
        float* ov = out_v + (size_t)node * 384 + 3 * f;
        ov[0] = av0; ov[1] = av1; ov[2] = av2;
    }
}

// ---------------- launch ----------------
extern "C" void kernel_launch(void* const* d_in, const int* in_sizes, int n_in,
                              void* d_out, int out_size) {
    (void)in_sizes; (void)n_in; (void)out_size;
    const float* s_j  = (const float*)d_in[0];
    const float* v_j  = (const float*)d_in[1];
    const float* r_ij = (const float*)d_in[2];
    const void*  nbrs = d_in[3];
    const float* W1   = (const float*)d_in[4];
    const float* b1   = (const float*)d_in[5];
    const float* W2   = (const float*)d_in[6];
    const float* b2   = (const float*)d_in[7];
    const float* Wd   = (const float*)d_in[8];
    const float* bd   = (const float*)d_in[9];
    float* out   = (float*)d_out;
    float* out_s = out;                              // [N,128]
    float* out_v = out + (size_t)N_NODESC * FEATC;   // [N,128,3]

    zero_kernel<<<(N_NODESC + 255) / 256, 256>>>();
    detect_kernel<<<1, 1024>>>((const int*)nbrs);
    extract_kernel<<<(N_EDGESC + 255) / 256, 256>>>(nbrs);
    vtrans_kernel<<<N_NODESC, 128>>>(v_j);
    phi_kernel<<<N_NODESC / 32, 128>>>(s_j, W1, b1, W2, b2);
    scan_kernel<<<1, 1024>>>();
    scatter_kernel<<<(N_EDGESC + 255) / 256, 256>>>();
    accum_kernel<<<1184, 128>>>(r_ij, Wd, bd, out_s, out_v);
}

// round 13
// speedup vs baseline: 1.2717x; 1.2717x over previous
#include <cuda_runtime.h>
#include <math.h>

#define N_NODESC 20000
#define N_EDGESC 640000
#define FEATC    128
#define N_RBFC   20
#define CUTOFFC  5.0f
#define PIF      3.14159265358979323846f

typedef unsigned long long u64;

// ---------------- f32x2 packed helpers ----------------
__device__ __forceinline__ u64 pack2(float lo, float hi) {
    u64 r; asm("mov.b64 %0, {%1,%2};" : "=l"(r) : "f"(lo), "f"(hi)); return r;
}
__device__ __forceinline__ void unpack2(u64 p, float& lo, float& hi) {
    asm("mov.b64 {%0,%1}, %2;" : "=f"(lo), "=f"(hi) : "l"(p));
}
__device__ __forceinline__ u64 fma2(u64 a, u64 b, u64 c) {
    u64 d; asm("fma.rn.f32x2 %0, %1, %2, %3;" : "=l"(d) : "l"(a), "l"(b), "l"(c)); return d;
}
__device__ __forceinline__ u64 add2(u64 a, u64 b) {
    u64 d; asm("add.rn.f32x2 %0, %1, %2;" : "=l"(d) : "l"(a), "l"(b)); return d;
}

// ---------------- scratch (__device__ globals; no allocation) ----------------
__device__ __align__(16) float g_phi[N_NODESC * 3 * FEATC];   // phi_node, [N,384]
__device__ __align__(16) int   g_count[N_NODESC];
__device__ __align__(16) int   g_cursor[N_NODESC];
__device__ __align__(16) int   g_rowptr[N_NODESC + 1];
__device__ __align__(16) int   g_eid[N_EDGESC];
__device__ __align__(16) int   g_src[N_EDGESC];
__device__ __align__(16) int   g_dst[N_EDGESC];
__device__ int g_flag;   // 0 -> nbrs is int64, nonzero -> int32

// ---------------- zero counters ----------------
__global__ void zero_kernel() {
    int i = blockIdx.x * blockDim.x + threadIdx.x;
    if (i < N_NODESC) { g_count[i] = 0; g_cursor[i] = 0; }
    if (i == 0) g_flag = 0;
}

// ---------------- dtype probe ----------------
__global__ void detect_kernel(const int* __restrict__ nbrs32) {
    int t = threadIdx.x;
    int v = nbrs32[2 * t + 1];
    __shared__ int red[1024];
    red[t] = v;
    __syncthreads();
    for (int off = 512; off > 0; off >>= 1) {
        if (t < off) red[t] |= red[t + off];
        __syncthreads();
    }
    if (t == 0) g_flag = red[0];
}

// ---------------- normalize indices to int32 SoA + degree count ----------------
__global__ void extract_kernel(const void* __restrict__ nbrs) {
    int e = blockIdx.x * blockDim.x + threadIdx.x;
    if (e >= N_EDGESC) return;
    int si, di;
    if (g_flag != 0) {
        const int* p = (const int*)nbrs;
        si = p[2 * e]; di = p[2 * e + 1];
    } else {
        const long long* p = (const long long*)nbrs;
        si = (int)p[2 * (long long)e]; di = (int)p[2 * (long long)e + 1];
    }
    g_src[e] = si;
    g_dst[e] = di;
    atomicAdd(&g_count[si], 1);
}

// ---------------- fused node MLP: phi = silu(s@W1+b1)@W2 + b2 ----------------
// 128 threads, 32 nodes/block. Thread tile: 4 nodes x 8 cols, f32x2 packed FMA.
#define SPAD 132
__global__ __launch_bounds__(128) void phi_kernel(
    const float* __restrict__ s,
    const float* __restrict__ W1, const float* __restrict__ b1,
    const float* __restrict__ W2, const float* __restrict__ b2)
{
    __shared__ __align__(16) float s_sm[32][SPAD];
    __shared__ __align__(16) float h_sm[32][SPAD];
    int tid = threadIdx.x;
    int node0 = blockIdx.x * 32;

    {
        const float4* s4 = (const float4*)(s + (size_t)node0 * FEATC);
        for (int idx = tid; idx < 32 * 32; idx += 128) {
            int row = idx >> 5, c = idx & 31;
            *(float4*)&s_sm[row][c * 4] = s4[row * 32 + c];
        }
    }
    __syncthreads();

    int cx = tid & 15;    // col octet: cols 8cx..8cx+7
    int ny = tid >> 4;    // node quad: rows 4ny..4ny+3

    // ---- stage 1: h = silu(s@W1 + b1) ----
    {
        u64 acc[4][4];
        #pragma unroll
        for (int i = 0; i < 4; i++)
            #pragma unroll
            for (int p = 0; p < 4; p++) acc[i][p] = 0ull;
        const ulonglong2* W1q = (const ulonglong2*)W1;  // 32 u2 per row
        #pragma unroll 4
        for (int k = 0; k < FEATC; k += 2) {
            ulonglong2 wA0 = W1q[(size_t)k * 32 + 2 * cx];
            ulonglong2 wA1 = W1q[(size_t)k * 32 + 2 * cx + 1];
            ulonglong2 wB0 = W1q[(size_t)(k + 1) * 32 + 2 * cx];
            ulonglong2 wB1 = W1q[(size_t)(k + 1) * 32 + 2 * cx + 1];
            #pragma unroll
            for (int i = 0; i < 4; i++) {
                float2 a2 = *(const float2*)&s_sm[ny * 4 + i][k];
                u64 aA = pack2(a2.x, a2.x);
                u64 aB = pack2(a2.y, a2.y);
                acc[i][0] = fma2(aA, wA0.x, acc[i][0]);
                acc[i][1] = fma2(aA, wA0.y, acc[i][1]);
                acc[i][2] = fma2(aA, wA1.x, acc[i][2]);
                acc[i][3] = fma2(aA, wA1.y, acc[i][3]);
                acc[i][0] = fma2(aB, wB0.x, acc[i][0]);
                acc[i][1] = fma2(aB, wB0.y, acc[i][1]);
                acc[i][2] = fma2(aB, wB1.x, acc[i][2]);
                acc[i][3] = fma2(aB, wB1.y, acc[i][3]);
            }
        }
        float2 bv[4];
        #pragma unroll
        for (int p = 0; p < 4; p++) bv[p] = *(const float2*)&b1[cx * 8 + p * 2];
        #pragma unroll
        for (int i = 0; i < 4; i++) {
            float h[8];
            #pragma unroll
            for (int p = 0; p < 4; p++) {
                float lo, hi; unpack2(acc[i][p], lo, hi);
                float x0 = lo + bv[p].x, x1 = hi + bv[p].y;
                h[2 * p]     = x0 / (1.0f + expf(-x0));
                h[2 * p + 1] = x1 / (1.0f + expf(-x1));
            }
            *(float4*)&h_sm[ny * 4 + i][cx * 8]     = make_float4(h[0], h[1], h[2], h[3]);
            *(float4*)&h_sm[ny * 4 + i][cx * 8 + 4] = make_float4(h[4], h[5], h[6], h[7]);
        }
    }
    __syncthreads();

    // ---- stage 2: phi = h@W2 + b2 (3 col-groups of 128) ----
    const ulonglong2* W2q = (const ulonglong2*)W2;  // 96 u2 per row
    for (int g = 0; g < 3; g++) {
        u64 acc[4][4];
        #pragma unroll
        for (int i = 0; i < 4; i++)
            #pragma unroll
            for (int p = 0; p < 4; p++) acc[i][p] = 0ull;
        #pragma unroll 4
        for (int k = 0; k < FEATC; k += 2) {
            ulonglong2 wA0 = W2q[(size_t)k * 96 + g * 32 + 2 * cx];
            ulonglong2 wA1 = W2q[(size_t)k * 96 + g * 32 + 2 * cx + 1];
            ulonglong2 wB0 = W2q[(size_t)(k + 1) * 96 + g * 32 + 2 * cx];
            ulonglong2 wB1 = W2q[(size_t)(k + 1) * 96 + g * 32 + 2 * cx + 1];
            #pragma unroll
            for (int i = 0; i < 4; i++) {
                float2 a2 = *(const float2*)&h_sm[ny * 4 + i][k];
                u64 aA = pack2(a2.x, a2.x);
                u64 aB = pack2(a2.y, a2.y);
                acc[i][0] = fma2(aA, wA0.x, acc[i][0]);
                acc[i][1] = fma2(aA, wA0.y, acc[i][1]);
                acc[i][2] = fma2(aA, wA1.x, acc[i][2]);
                acc[i][3] = fma2(aA, wA1.y, acc[i][3]);
                acc[i][0] = fma2(aB, wB0.x, acc[i][0]);
                acc[i][1] = fma2(aB, wB0.y, acc[i][1]);
                acc[i][2] = fma2(aB, wB1.x, acc[i][2]);
                acc[i][3] = fma2(aB, wB1.y, acc[i][3]);
            }
        }
        float2 bv[4];
        #pragma unroll
        for (int p = 0; p < 4; p++) bv[p] = *(const float2*)&b2[g * 128 + cx * 8 + p * 2];
        #pragma unroll
        for (int i = 0; i < 4; i++) {
            float o[8];
            #pragma unroll
            for (int p = 0; p < 4; p++) {
                float lo, hi; unpack2(acc[i][p], lo, hi);
                o[2 * p]     = lo + bv[p].x;
                o[2 * p + 1] = hi + bv[p].y;
            }
            float* dst = &g_phi[(size_t)(node0 + ny * 4 + i) * 384 + g * 128 + cx * 8];
            *(float4*)dst       = make_float4(o[0], o[1], o[2], o[3]);
            *(float4*)(dst + 4) = make_float4(o[4], o[5], o[6], o[7]);
        }
    }
}

// ---------------- CSR scan (2-level shfl scan, 20 items/thread) ----------------
__global__ void scan_kernel() {
    const int PER = 20;
    int t = threadIdx.x;
    int lane = t & 31, wid = t >> 5;
    int base = t * PER;
    int pre[PER];
    int s = 0;
    #pragma unroll
    for (int i = 0; i < PER; i++) {
        int idx = base + i;
        int v = (idx < N_NODESC) ? g_count[idx] : 0;
        pre[i] = s;
        s += v;
    }
    int x = s;
    #pragma unroll
    for (int off = 1; off < 32; off <<= 1) {
        int y = __shfl_up_sync(0xffffffffu, x, off);
        if (lane >= off) x += y;
    }
    __shared__ int wsum[32];
    if (lane == 31) wsum[wid] = x;
    __syncthreads();
    if (wid == 0) {
        int w = wsum[lane];
        #pragma unroll
        for (int off = 1; off < 32; off <<= 1) {
            int y = __shfl_up_sync(0xffffffffu, w, off);
            if (lane >= off) w += y;
        }
        wsum[lane] = w;
    }
    __syncthreads();
    int thread_pref = (x - s) + (wid > 0 ? wsum[wid - 1] : 0);
    #pragma unroll
    for (int i = 0; i < PER; i++) {
        int idx = base + i;
        if (idx < N_NODESC) g_rowptr[idx] = thread_pref + pre[i];
    }
    if (t == 1023) g_rowptr[N_NODESC] = wsum[31];
}

__global__ void scatter_kernel() {
    int e = blockIdx.x * blockDim.x + threadIdx.x;
    if (e < N_EDGESC) {
        int i = g_src[e];
        int pos = g_rowptr[i] + atomicAdd(&g_cursor[i], 1);
        g_eid[pos] = e;
    }
}

// ---------------- node-parallel accumulate ----------------
// 128 threads, 1 feature/thread. FFMA2 dot. Edge-PAIR processing: two
// independent dot chains per iteration (2x ILP), prefetch pair e+2/e+3.
#define STAGE 64
#define GPAD  24
__global__ __launch_bounds__(128, 4) void accum_kernel(
    const float* __restrict__ v_j, const float* __restrict__ r_ij,
    const float* __restrict__ Wd, const float* __restrict__ bd,
    float* __restrict__ out_s, float* __restrict__ out_v)
{
    __shared__ __align__(16) float sm_g[STAGE][GPAD];   // rbf_k = sin(kx)/d
    __shared__ __align__(16) float4 sm_geo[STAGE];      // u0,u1,u2,env
    __shared__ int sm_j[STAGE];

    int f = threadIdx.x;

    u64 wdA[10], wdB[10], wdC[10];
    #pragma unroll
    for (int i = 0; i < 10; i++) {
        wdA[i] = pack2(Wd[(2 * i) * 384 + f],       Wd[(2 * i + 1) * 384 + f]);
        wdB[i] = pack2(Wd[(2 * i) * 384 + 128 + f], Wd[(2 * i + 1) * 384 + 128 + f]);
        wdC[i] = pack2(Wd[(2 * i) * 384 + 256 + f], Wd[(2 * i + 1) * 384 + 256 + f]);
    }
    float bd0 = bd[f], bd1 = bd[128 + f], bd2 = bd[256 + f];

    for (int node = blockIdx.x; node < N_NODESC; node += gridDim.x) {
        int start = g_rowptr[node];
        int end   = g_rowptr[node + 1];
        float accs = 0.0f, av0 = 0.0f, av1 = 0.0f, av2 = 0.0f;

        for (int base = start; base < end; base += STAGE) {
            int n = end - base; if (n > STAGE) n = STAGE;
            __syncthreads();
            // phase A: stage per-edge geometry + raw rbf (one thread per edge)
            if (f < n) {
                int eid = g_eid[base + f];
                float r0 = r_ij[3 * (size_t)eid + 0];
                float r1 = r_ij[3 * (size_t)eid + 1];
                float r2 = r_ij[3 * (size_t)eid + 2];
                float d2 = r0 * r0 + r1 * r1 + r2 * r2 + 3e-15f;
                float d  = sqrtf(d2);
                float rinv = 1.0f / d;
                float x = (PIF / CUTOFFC) * d;
                float sx, cxx;
                sincosf(x, &sx, &cxx);
                float env = (d < CUTOFFC) ? 0.5f * (cxx + 1.0f) : 0.0f;
                sm_geo[f] = make_float4(r0 * rinv, r1 * rinv, r2 * rinv, env);
                float twoc = 2.0f * cxx;
                float sp = 0.0f, sc = sx;
                #pragma unroll
                for (int k = 0; k < N_RBFC; k++) {
                    sm_g[f][k] = sc * rinv;  // env applied at consume time
                    float sn = twoc * sc - sp;
                    sp = sc; sc = sn;
                }
                sm_j[f] = g_dst[eid];
            }
            __syncthreads();

            // phase B: edge pairs with 2 independent dot chains
            float p0[2], p1[2], p2[2], vx[2], vy[2], vz[2];
            {
                int j0 = sm_j[0];
                const float* ph = g_phi + (size_t)j0 * 384 + f;
                p0[0] = ph[0]; p1[0] = ph[128]; p2[0] = ph[256];
                const float* vv = v_j + (size_t)j0 * 384 + 3 * f;
                vx[0] = vv[0]; vy[0] = vv[1]; vz[0] = vv[2];
            }
            if (n > 1) {
                int j1 = sm_j[1];
                const float* ph = g_phi + (size_t)j1 * 384 + f;
                p0[1] = ph[0]; p1[1] = ph[128]; p2[1] = ph[256];
                const float* vv = v_j + (size_t)j1 * 384 + 3 * f;
                vx[1] = vv[0]; vy[1] = vv[1]; vz[1] = vv[2];
            }
            for (int e = 0; e < n; e += 2) {
                bool two = (e + 1 < n);
                // take current pair's prefetched values
                float cp0A = p0[0], cp1A = p1[0], cp2A = p2[0];
                float cvxA = vx[0], cvyA = vy[0], cvzA = vz[0];
                float cp0B = p0[1], cp1B = p1[1], cp2B = p2[1];
                float cvxB = vx[1], cvyB = vy[1], cvzB = vz[1];
                // prefetch pair e+2 / e+3
                if (e + 2 < n) {
                    int jn = sm_j[e + 2];
                    const float* ph = g_phi + (size_t)jn * 384 + f;
                    p0[0] = ph[0]; p1[0] = ph[128]; p2[0] = ph[256];
                    const float* vv = v_j + (size_t)jn * 384 + 3 * f;
                    vx[0] = vv[0]; vy[0] = vv[1]; vz[0] = vv[2];
                }
                if (e + 3 < n) {
                    int jn = sm_j[e + 3];
                    const float* ph = g_phi + (size_t)jn * 384 + f;
                    p0[1] = ph[0]; p1[1] = ph[128]; p2[1] = ph[256];
                    const float* vv = v_j + (size_t)jn * 384 + 3 * f;
                    vx[1] = vv[0]; vy[1] = vv[1]; vz[1] = vv[2];
                }
                // two independent FFMA2 dot chains (ptxas interleaves)
                const ulonglong2* gqA = (const ulonglong2*)&sm_g[e][0];
                ulonglong2 qa = gqA[0], qb = gqA[1], qc = gqA[2], qd = gqA[3], qe = gqA[4];
                int e2 = two ? (e + 1) : e;
                const ulonglong2* gqB = (const ulonglong2*)&sm_g[e2][0];
                ulonglong2 ra = gqB[0], rb = gqB[1], rc = gqB[2], rd = gqB[3], re = gqB[4];

                u64 a0, a1, b0, b1, c0, c1;
                u64 d0, d1, e0, e1, f0v, f1v;
                a0 = fma2(qa.x, wdA[0], 0ull); a1 = fma2(qa.y, wdA[1], 0ull);
                d0 = fma2(ra.x, wdA[0], 0ull); d1 = fma2(ra.y, wdA[1], 0ull);
                b0 = fma2(qa.x, wdB[0], 0ull); b1 = fma2(qa.y, wdB[1], 0ull);
                e0 = fma2(ra.x, wdB[0], 0ull); e1 = fma2(ra.y, wdB[1], 0ull);
                c0 = fma2(qa.x, wdC[0], 0ull); c1 = fma2(qa.y, wdC[1], 0ull);
                f0v = fma2(ra.x, wdC[0], 0ull); f1v = fma2(ra.y, wdC[1], 0ull);

                a0 = fma2(qb.x, wdA[2], a0);   a1 = fma2(qb.y, wdA[3], a1);
                d0 = fma2(rb.x, wdA[2], d0);   d1 = fma2(rb.y, wdA[3], d1);
                b0 = fma2(qb.x, wdB[2], b0);   b1 = fma2(qb.y, wdB[3], b1);
                e0 = fma2(rb.x, wdB[2], e0);   e1 = fma2(rb.y, wdB[3], e1);
                c0 = fma2(qb.x, wdC[2], c0);   c1 = fma2(qb.y, wdC[3], c1);
                f0v = fma2(rb.x, wdC[2], f0v); f1v = fma2(rb.y, wdC[3], f1v);

                a0 = fma2(qc.x, wdA[4], a0);   a1 = fma2(qc.y, wdA[5], a1);
                d0 = fma2(rc.x, wdA[4], d0);   d1 = fma2(rc.y, wdA[5], d1);
                b0 = fma2(qc.x, wdB[4], b0);   b1 = fma2(qc.y, wdB[5], b1);
                e0 = fma2(rc.x, wdB[4], e0);   e1 = fma2(rc.y, wdB[5], e1);
                c0 = fma2(qc.x, wdC[4], c0);   c1 = fma2(qc.y, wdC[5], c1);
                f0v = fma2(rc.x, wdC[4], f0v); f1v = fma2(rc.y, wdC[5], f1v);

                a0 = fma2(qd.x, wdA[6], a0);   a1 = fma2(qd.y, wdA[7], a1);
                d0 = fma2(rd.x, wdA[6], d0);   d1 = fma2(rd.y, wdA[7], d1);
                b0 = fma2(qd.x, wdB[6], b0);   b1 = fma2(qd.y, wdB[7], b1);
                e0 = fma2(rd.x, wdB[6], e0);   e1 = fma2(rd.y, wdB[7], e1);
                c0 = fma2(qd.x, wdC[6], c0);   c1 = fma2(qd.y, wdC[7], c1);
                f0v = fma2(rd.x, wdC[6], f0v); f1v = fma2(rd.y, wdC[7], f1v);

                a0 = fma2(qe.x, wdA[8], a0);   a1 = fma2(qe.y, wdA[9], a1);
                d0 = fma2(re.x, wdA[8], d0);   d1 = fma2(re.y, wdA[9], d1);
                b0 = fma2(qe.x, wdB[8], b0);   b1 = fma2(qe.y, wdB[9], b1);
                e0 = fma2(re.x, wdB[8], e0);   e1 = fma2(re.y, wdB[9], e1);
                c0 = fma2(qe.x, wdC[8], c0);   c1 = fma2(qe.y, wdC[9], c1);
                f0v = fma2(re.x, wdC[8], f0v); f1v = fma2(re.y, wdC[9], f1v);

                float4 geoA = sm_geo[e];
                float lo, hi;
                unpack2(add2(a0, a1), lo, hi); float ws0A = (lo + hi + bd0) * geoA.w;
                unpack2(add2(b0, b1), lo, hi); float ws1A = (lo + hi + bd1) * geoA.w;
                unpack2(add2(c0, c1), lo, hi); float ws2A = (lo + hi + bd2) * geoA.w;
                float i0A = cp0A * ws0A;
                float i2A = cp2A * ws2A;
                accs += cp1A * ws1A;
                av0 += i2A * geoA.x; av0 += i0A * cvxA;
                av1 += i2A * geoA.y; av1 += i0A * cvyA;
                av2 += i2A * geoA.z; av2 += i0A * cvzA;

                if (two) {
                    float4 geoB = sm_geo[e + 1];
                    unpack2(add2(d0, d1), lo, hi); float ws0B = (lo + hi + bd0) * geoB.w;
                    unpack2(add2(e0, e1), lo, hi); float ws1B = (lo + hi + bd1) * geoB.w;
                    unpack2(add2(f0v, f1v), lo, hi); float ws2B = (lo + hi + bd2) * geoB.w;
                    float i0B = cp0B * ws0B;
                    float i2B = cp2B * ws2B;
                    accs += cp1B * ws1B;
                    av0 += i2B * geoB.x; av0 += i0B * cvxB;
                    av1 += i2B * geoB.y; av1 += i0B * cvyB;
                    av2 += i2B * geoB.z; av2 += i0B * cvzB;
                }
            }
        }
        out_s[(size_t)node * FEATC + f] = accs;
        float* ov = out_v + (size_t)node * 384 + 3 * f;
        ov[0] = av0; ov[1] = av1; ov[2] = av2;
    }
}

// ---------------- launch ----------------
extern "C" void kernel_launch(void* const* d_in, const int* in_sizes, int n_in,
                              void* d_out, int out_size) {
    (void)in_sizes; (void)n_in; (void)out_size;
    const float* s_j  = (const float*)d_in[0];
    const float* v_j  = (const float*)d_in[1];
    const float* r_ij = (const float*)d_in[2];
    const void*  nbrs = d_in[3];
    const float* W1   = (const float*)d_in[4];
    const float* b1   = (const float*)d_in[5];
    const float* W2   = (const float*)d_in[6];
    const float* b2   = (const float*)d_in[7];
    const float* Wd   = (const float*)d_in[8];
    const float* bd   = (const float*)d_in[9];
    float* out   = (float*)d_out;
    float* out_s = out;                              // [N,128]
    float* out_v = out + (size_t)N_NODESC * FEATC;   // [N,128,3]

    zero_kernel<<<(N_NODESC + 255) / 256, 256>>>();
    detect_kernel<<<1, 1024>>>((const int*)nbrs);
    extract_kernel<<<(N_EDGESC + 255) / 256, 256>>>(nbrs);
    phi_kernel<<<N_NODESC / 32, 128>>>(s_j, W1, b1, W2, b2);
    scan_kernel<<<1, 1024>>>();
    scatter_kernel<<<(N_EDGESC + 255) / 256, 256>>>();
    accum_kernel<<<1184, 128>>>(v_j, r_ij, Wd, bd, out_s, out_v);
}